// round 15
// baseline (speedup 1.0000x reference)
#include <cuda_runtime.h>
#include <cuda_fp16.h>
#include <math.h>
#include <stdint.h>

// Problem constants (fixed by the dataset)
#define NNODES 50000
#define HDIM   768
#define D1DIM  256
#define NOUT   512        // 2*D1: [A | B] per node
#define NEDGES 200000

// GEMM tiling: 128x128 block, BK=32, fp16 mma.sync m16n8k16, 3-stage cp.async
#define BM 128
#define BN 128
#define BK 32
#define LDH 40            // smem row stride in halves (80B); conflict-free ldmatrix
#define NSTAGE 3
#define STAGE_H (BM * LDH)            // halves per tile stage (5120)

// M-chunking for conv/gemm overlap
#define NODE_SPLIT 25088                                  // chunk0 nodes (196 tiles)
#define GB0 (NODE_SPLIT / BM)                             // 196
#define GB1 ((NNODES + BM - 1) / BM - GB0)                // 195

#define EDGE_WARPS 8
#define EDGES_PER_WARP 4
#define EDGES_PER_BLOCK (EDGE_WARPS * EDGES_PER_WARP)     // 32
#define EDGE_BLOCKS (NEDGES / EDGES_PER_BLOCK)            // 6250

// conv_x: 4 strided float4 per thread for MLP
#define CVX_UNROLL 4
#define CVX_C0 ((size_t)NODE_SPLIT * HDIM / 4)            // 4,816,896 float4
#define CVX_C1 ((size_t)(NNODES - NODE_SPLIT) * HDIM / 4) // 4,783,104 float4
#define CVX_B0 ((int)((CVX_C0 + 256 * CVX_UNROLL - 1) / (256 * CVX_UNROLL)))
#define CVX_B1 ((int)((CVX_C1 + 256 * CVX_UNROLL - 1) / (256 * CVX_UNROLL)))

// Scratch (static device globals; no runtime allocation)
__device__ __half g_xh[(size_t)NNODES * HDIM];       // x in fp16 (~77 MB)
__device__ __half g_Wh[(size_t)NOUT * HDIM];         // Wcat rows in fp16 (768 KB)
__device__ __half g_AB[(size_t)NNODES * NOUT];       // ~51 MB -> L2-resident
__device__ float  g_partials[2 * EDGE_BLOCKS];

// ---------------------------------------------------------------------------
// helpers
// ---------------------------------------------------------------------------
__device__ __forceinline__ void cp_async16(void* smem, const void* gmem) {
    unsigned s = (unsigned)__cvta_generic_to_shared(smem);
    asm volatile("cp.async.cg.shared.global [%0], [%1], 16;" :: "r"(s), "l"(gmem));
}
#define CP_COMMIT  asm volatile("cp.async.commit_group;")
#define CP_WAIT1   asm volatile("cp.async.wait_group 1;")
#define CP_WAIT0   asm volatile("cp.async.wait_group 0;")

__device__ __forceinline__ void ldsm_x4(unsigned& r0, unsigned& r1,
                                        unsigned& r2, unsigned& r3, unsigned addr) {
    asm volatile("ldmatrix.sync.aligned.m8n8.x4.shared.b16 {%0,%1,%2,%3}, [%4];"
                 : "=r"(r0), "=r"(r1), "=r"(r2), "=r"(r3) : "r"(addr));
}

#define MMA_F16(c, a, b)                                                      \
    asm volatile(                                                             \
        "mma.sync.aligned.m16n8k16.row.col.f32.f16.f16.f32 "                  \
        "{%0,%1,%2,%3},{%4,%5,%6,%7},{%8,%9},{%0,%1,%2,%3};"                  \
        : "+f"((c)[0]), "+f"((c)[1]), "+f"((c)[2]), "+f"((c)[3])              \
        : "r"((a)[0]), "r"((a)[1]), "r"((a)[2]), "r"((a)[3]),                 \
          "r"((b)[0]), "r"((b)[1]))

// packed half2 tanh on the MUFU pipe
__device__ __forceinline__ __half2 tanh_h2(__half2 x) {
    __half2 y;
    asm("tanh.approx.f16x2 %0, %1;"
        : "=r"(reinterpret_cast<unsigned&>(y))
        : "r"(reinterpret_cast<unsigned&>(x)));
    return y;
}

// ---------------------------------------------------------------------------
// Conversion pre-passes: fp32 -> fp16 globals (chunked for overlap)
// ---------------------------------------------------------------------------
__global__ __launch_bounds__(256) void conv_x_kernel(const float* __restrict__ x,
                                                     size_t base, size_t count,
                                                     int nblocks)
{
    const size_t stride = (size_t)nblocks * 256;
    const size_t i = (size_t)blockIdx.x * 256 + threadIdx.x;
    float4 v[CVX_UNROLL];
    bool ok[CVX_UNROLL];
    size_t idx[CVX_UNROLL];
    #pragma unroll
    for (int u = 0; u < CVX_UNROLL; u++) {
        const size_t off = i + (size_t)u * stride;
        ok[u]  = off < count;
        idx[u] = base + off;
        if (ok[u]) v[u] = *(const float4*)(x + idx[u] * 4);
    }
    #pragma unroll
    for (int u = 0; u < CVX_UNROLL; u++) {
        if (ok[u]) {
            __half2 h0 = __floats2half2_rn(v[u].x, v[u].y);
            __half2 h1 = __floats2half2_rn(v[u].z, v[u].w);
            uint2 o; o.x = *(uint32_t*)&h0; o.y = *(uint32_t*)&h1;
            *(uint2*)(g_xh + idx[u] * 4) = o;
        }
    }
}

__global__ __launch_bounds__(256) void conv_w_kernel(const float* __restrict__ W1)
{
    const int i = blockIdx.x * 256 + threadIdx.x;   // float4 index
    const int n4 = NOUT * HDIM / 4;
    if (i < n4) {
        const int e = i * 4;
        const int n = e / HDIM;
        const int k = e % HDIM;
        const float* src = (n < D1DIM)
            ? (W1 + (size_t)n * (2 * HDIM) + k)
            : (W1 + (size_t)(n - D1DIM) * (2 * HDIM) + HDIM + k);
        float4 v = *(const float4*)src;
        __half2 h0 = __floats2half2_rn(v.x, v.y);
        __half2 h1 = __floats2half2_rn(v.z, v.w);
        uint2 o; o.x = *(uint32_t*)&h0; o.y = *(uint32_t*)&h1;
        *(uint2*)(g_Wh + e) = o;
    }
}

// ---------------------------------------------------------------------------
// Kernel 1: AB = x_h @ W_h^T via fp16 mma.sync m16n8k16 (fp32 accumulate).
// 3-stage cp.async pipeline, ldmatrix.x4 b16 fragment loads.
// Epilogue folds b1 into the A-half (n0 < 256) in fp32 before fp16 rounding.
// moff: m-tile offset for chunked launches.
// ---------------------------------------------------------------------------
__global__ __launch_bounds__(256) void gemm_kernel(const float* __restrict__ b1,
                                                   int moff)
{
    extern __shared__ __align__(16) __half smem[];
    __half* sA = smem;
    __half* sB = smem + NSTAGE * STAGE_H;

    const int tid  = threadIdx.x;
    const int lane = tid & 31;
    const int warp = tid >> 5;
    const int wm   = (warp >> 2) * 64;
    const int wn   = (warp & 3) * 32;

    const int m0 = (blockIdx.x + moff) * BM;
    const int n0 = blockIdx.y * BN;

    const int row0 = tid >> 2;             // 0..63
    const int c4   = tid & 3;
    const int row1 = row0 + 64;
    int gm0 = m0 + row0; if (gm0 > NNODES - 1) gm0 = NNODES - 1;
    int gm1 = m0 + row1; if (gm1 > NNODES - 1) gm1 = NNODES - 1;
    const __half* pA0 = g_xh + (size_t)gm0 * HDIM + c4 * 8;
    const __half* pA1 = g_xh + (size_t)gm1 * HDIM + c4 * 8;
    const __half* pB0 = g_Wh + (size_t)(n0 + row0) * HDIM + c4 * 8;
    const __half* pB1 = g_Wh + (size_t)(n0 + row1) * HDIM + c4 * 8;

    unsigned smA[NSTAGE], smB[NSTAGE];
    #pragma unroll
    for (int st = 0; st < NSTAGE; st++) {
        smA[st] = (unsigned)__cvta_generic_to_shared(sA + st * STAGE_H);
        smB[st] = (unsigned)__cvta_generic_to_shared(sB + st * STAGE_H);
    }

    const int aRow = wm + (lane & 15);
    const unsigned aKB = (unsigned)(lane >> 4) * 16u;
    const int bRow = wn + ((lane >> 4) & 1) * 8 + (lane & 7);
    const unsigned bKB = (unsigned)((lane >> 3) & 1) * 16u;

    float acc[4][4][4];
    #pragma unroll
    for (int i = 0; i < 4; i++)
        #pragma unroll
        for (int j = 0; j < 4; j++)
            #pragma unroll
            for (int v = 0; v < 4; v++) acc[i][j][v] = 0.f;

    #pragma unroll
    for (int st = 0; st < 2; st++) {
        const int kt = st * BK;
        cp_async16(sA + st * STAGE_H + row0 * LDH + c4 * 8, pA0 + kt);
        cp_async16(sA + st * STAGE_H + row1 * LDH + c4 * 8, pA1 + kt);
        cp_async16(sB + st * STAGE_H + row0 * LDH + c4 * 8, pB0 + kt);
        cp_async16(sB + st * STAGE_H + row1 * LDH + c4 * 8, pB1 + kt);
        CP_COMMIT;
    }

    const int NIT = HDIM / BK;  // 24
    int s = 0;
    for (int it = 0; it < NIT; ++it) {
        if (it < NIT - 1) { CP_WAIT1; } else { CP_WAIT0; }
        __syncthreads();

        if (it + 2 < NIT) {
            const int st = (it + 2) % NSTAGE;
            const int kt = (it + 2) * BK;
            cp_async16(sA + st * STAGE_H + row0 * LDH + c4 * 8, pA0 + kt);
            cp_async16(sA + st * STAGE_H + row1 * LDH + c4 * 8, pA1 + kt);
            cp_async16(sB + st * STAGE_H + row0 * LDH + c4 * 8, pB0 + kt);
            cp_async16(sB + st * STAGE_H + row1 * LDH + c4 * 8, pB1 + kt);
            CP_COMMIT;
        }

        const unsigned bA = smA[s];
        const unsigned bB = smB[s];
        #pragma unroll
        for (int kk = 0; kk < 2; kk++) {
            unsigned af[4][4], bf[4][2];
            #pragma unroll
            for (int mi = 0; mi < 4; mi++) {
                unsigned addr = bA + (unsigned)(aRow + mi * 16) * (LDH * 2)
                              + (unsigned)kk * 32u + aKB;
                ldsm_x4(af[mi][0], af[mi][1], af[mi][2], af[mi][3], addr);
            }
            #pragma unroll
            for (int p = 0; p < 2; p++) {
                unsigned addr = bB + (unsigned)(bRow + p * 16) * (LDH * 2)
                              + (unsigned)kk * 32u + bKB;
                ldsm_x4(bf[2 * p][0], bf[2 * p][1], bf[2 * p + 1][0], bf[2 * p + 1][1], addr);
            }
            #pragma unroll
            for (int mi = 0; mi < 4; mi++)
                #pragma unroll
                for (int ni = 0; ni < 4; ni++)
                    MMA_F16(acc[mi][ni], af[mi], bf[ni]);
        }
        s = (s + 1 == NSTAGE) ? 0 : s + 1;
    }

    // ---- epilogue: fold b1 into A-half, store fp16 ----
    const int g  = lane >> 2;
    const int tg = lane & 3;
    const bool isA = (n0 < D1DIM);         // uniform per block (BN=128)
    float2 bv[4];
    #pragma unroll
    for (int ni = 0; ni < 4; ni++) {
        const int gn = n0 + wn + ni * 8 + 2 * tg;
        bv[ni] = isA ? *(const float2*)(b1 + gn) : make_float2(0.f, 0.f);
    }
    #pragma unroll
    for (int mi = 0; mi < 4; mi++) {
        #pragma unroll
        for (int ni = 0; ni < 4; ni++) {
            const int gm = m0 + wm + mi * 16 + g;
            const int gn = n0 + wn + ni * 8 + 2 * tg;
            if (gm < NNODES) {
                *(__half2*)(g_AB + (size_t)gm * NOUT + gn) =
                    __floats2half2_rn(acc[mi][ni][0] + bv[ni].x,
                                      acc[mi][ni][1] + bv[ni].y);
            }
            if (gm + 8 < NNODES) {
                *(__half2*)(g_AB + (size_t)(gm + 8) * NOUT + gn) =
                    __floats2half2_rn(acc[mi][ni][2] + bv[ni].x,
                                      acc[mi][ni][3] + bv[ni].y);
            }
        }
    }
}

// ---------------------------------------------------------------------------
// Kernel 2: per-edge MLP tail, packed half2, logit-difference form.
// ---------------------------------------------------------------------------
__global__ __launch_bounds__(256) void edge_kernel(const float* __restrict__ W2,
                                                   const float* __restrict__ b2,
                                                   const float* __restrict__ cw,
                                                   const int* __restrict__ esrc,
                                                   const int* __restrict__ edst,
                                                   const int* __restrict__ labels,
                                                   float* __restrict__ out)
{
    __shared__ __half2 s_wdh[D1DIM / 2];     // 0.5*(w1 - w0) in fp16
    __shared__ float s_wn[EDGE_WARPS];
    __shared__ float s_w[EDGE_WARPS];

    const int tid  = threadIdx.x;
    const int lane = tid & 31;
    const int warp = tid >> 5;

    if (tid < D1DIM / 2) {
        s_wdh[tid] = __floats2half2_rn(
            0.5f * (W2[D1DIM + 2 * tid]     - W2[2 * tid]),
            0.5f * (W2[D1DIM + 2 * tid + 1] - W2[2 * tid + 1]));
    }
    __syncthreads();

    const int eb = blockIdx.x * EDGES_PER_BLOCK + warp * EDGES_PER_WARP;
    const int j0 = lane * 8;          // 8 halves = 4 half2 per lane
    const int h0 = lane * 4;          // half2 base index

    // issue all 8 gathers before compute
    uint4 va[EDGES_PER_WARP], vb[EDGES_PER_WARP];
    #pragma unroll
    for (int q = 0; q < EDGES_PER_WARP; q++) {
        const int s = esrc[eb + q];
        const int d = edst[eb + q];
        va[q] = *(const uint4*)(g_AB + (size_t)s * NOUT + j0);
        vb[q] = *(const uint4*)(g_AB + (size_t)d * NOUT + D1DIM + j0);
    }

    const __half2 C0 = __float2half2_rn(0.7978845608f);
    const __half2 C1 = __float2half2_rn(0.0356774081f);

    __half2 acd[EDGES_PER_WARP];
    #pragma unroll
    for (int q = 0; q < EDGES_PER_WARP; q++) acd[q] = __float2half2_rn(0.f);

    #pragma unroll
    for (int t = 0; t < 4; t++) {
        const __half2 wd = s_wdh[h0 + t];
        #pragma unroll
        for (int q = 0; q < EDGES_PER_WARP; q++) {
            const __half2 a2  = ((const __half2*)&va[q])[t];   // b1 folded in
            const __half2 b2h = ((const __half2*)&vb[q])[t];
            const __half2 v  = __hadd2(a2, b2h);
            const __half2 w  = __hmul2(v, v);
            const __half2 u  = __hmul2(v, __hfma2(C1, w, C0));
            const __half2 th = tanh_h2(u);
            const __half2 h2 = __hfma2(v, th, v);              // = 2*gelu
            acd[q] = __hfma2(h2, wd, acd[q]);
        }
    }

    float r[EDGES_PER_WARP];
    #pragma unroll
    for (int q = 0; q < EDGES_PER_WARP; q++) {
        const float2 x = __half22float2(acd[q]);
        r[q] = x.x + x.y;
    }

    // folded butterfly reduce: lane l holds edge ((l>>4)&1)*2 + ((l>>3)&1)
    #pragma unroll
    for (int i = 0; i < 2; i++) {
        const float keep = (lane & 16) ? r[i + 2] : r[i];
        const float send = (lane & 16) ? r[i] : r[i + 2];
        r[i] = keep + __shfl_xor_sync(0xFFFFFFFFu, send, 16);
    }
    {
        const float keep = (lane & 8) ? r[1] : r[0];
        const float send = (lane & 8) ? r[0] : r[1];
        r[0] = keep + __shfl_xor_sync(0xFFFFFFFFu, send, 8);
    }
    r[0] += __shfl_xor_sync(0xFFFFFFFFu, r[0], 4);
    r[0] += __shfl_xor_sync(0xFFFFFFFFu, r[0], 2);
    r[0] += __shfl_xor_sync(0xFFFFFFFFu, r[0], 1);

    // parallel epilogue: lanes 0,8,16,24 each own one edge
    float wn = 0.f, wsum = 0.f;
    if ((lane & 7) == 0) {
        const int q = ((lane >> 4) & 1) * 2 + ((lane >> 3) & 1);
        const int e = eb + q;
        const float d = r[0] + (__ldg(&b2[1]) - __ldg(&b2[0]));
        const float ed  = __expf(-fabsf(d));
        const float inv = 1.0f / (1.0f + ed);
        const float pmx = inv;
        const float pmn = ed * inv;
        const float p1 = (d >= 0.f) ? pmx : pmn;
        const float p0 = (d >= 0.f) ? pmn : pmx;
        out[1 + 2 * e]     = p0;
        out[1 + 2 * e + 1] = p1;
        const int lb = labels[e];
        const float py = lb ? p1 : p0;
        const float w  = __ldg(&cw[lb]);
        wn   = -w * logf(py);
        wsum = w;
    }
    wn   += __shfl_xor_sync(0xFFFFFFFFu, wn, 8);
    wsum += __shfl_xor_sync(0xFFFFFFFFu, wsum, 8);
    wn   += __shfl_xor_sync(0xFFFFFFFFu, wn, 16);
    wsum += __shfl_xor_sync(0xFFFFFFFFu, wsum, 16);

    if (lane == 0) { s_wn[warp] = wn; s_w[warp] = wsum; }
    __syncthreads();
    if (tid == 0) {
        float a = 0.f, b = 0.f;
        #pragma unroll
        for (int i = 0; i < EDGE_WARPS; i++) { a += s_wn[i]; b += s_w[i]; }
        g_partials[blockIdx.x]               = a;
        g_partials[EDGE_BLOCKS + blockIdx.x] = b;
    }
}

// ---------------------------------------------------------------------------
// Kernel 3: deterministic final reduction -> loss at out[0]
// ---------------------------------------------------------------------------
__global__ __launch_bounds__(256) void finalize_kernel(float* __restrict__ out)
{
    __shared__ float sa[256];
    __shared__ float sb[256];
    const int tid = threadIdx.x;
    float a = 0.f, b = 0.f;
    for (int i = tid; i < EDGE_BLOCKS; i += 256) {
        a += g_partials[i];
        b += g_partials[EDGE_BLOCKS + i];
    }
    sa[tid] = a; sb[tid] = b;
    __syncthreads();
    for (int o = 128; o > 0; o >>= 1) {
        if (tid < o) { sa[tid] += sa[tid + o]; sb[tid] += sb[tid + o]; }
        __syncthreads();
    }
    if (tid == 0) out[0] = sa[0] / sb[0];
}

// ---------------------------------------------------------------------------
extern "C" void kernel_launch(void* const* d_in, const int* in_sizes, int n_in,
                              void* d_out, int out_size)
{
    const float* x      = (const float*)d_in[0];
    const float* W1     = (const float*)d_in[1];
    const float* b1     = (const float*)d_in[2];
    const float* W2     = (const float*)d_in[3];
    const float* b2     = (const float*)d_in[4];
    const float* cw     = (const float*)d_in[5];
    const int*   esrc   = (const int*)d_in[6];
    const int*   edst   = (const int*)d_in[7];
    const int*   labels = (const int*)d_in[8];
    float* out = (float*)d_out;

    const int GEMM_SMEM = 2 * NSTAGE * STAGE_H * (int)sizeof(__half);  // 61440
    cudaFuncSetAttribute(gemm_kernel,
                         cudaFuncAttributeMaxDynamicSharedMemorySize, GEMM_SMEM);

    // current stream (harness launches/captures on the default/legacy stream)
    cudaStream_t s0 = (cudaStream_t)0;

    // fork stream + events (created per call; kernel_launch only runs for
    // correctness + capture, replays re-execute the captured graph)
    cudaStream_t s1;
    cudaStreamCreateWithFlags(&s1, cudaStreamNonBlocking);
    cudaEvent_t evA, evB, evC;
    cudaEventCreateWithFlags(&evA, cudaEventDisableTiming);
    cudaEventCreateWithFlags(&evB, cudaEventDisableTiming);
    cudaEventCreateWithFlags(&evC, cudaEventDisableTiming);

    // S: conv_w, conv_x chunk0
    conv_w_kernel<<<(NOUT * HDIM / 4 + 255) / 256, 256, 0, s0>>>(W1);
    conv_x_kernel<<<CVX_B0, 256, 0, s0>>>(x, 0, CVX_C0, CVX_B0);
    cudaEventRecord(evA, s0);

    // fork: gemm chunk0 on s1 (needs conv_w + conv_x chunk0)
    cudaStreamWaitEvent(s1, evA, 0);
    {
        dim3 g0(GB0, NOUT / BN);
        gemm_kernel<<<g0, 256, GEMM_SMEM, s1>>>(b1, 0);
    }

    // S: conv_x chunk1 (overlaps gemm chunk0)
    conv_x_kernel<<<CVX_B1, 256, 0, s0>>>(x, CVX_C0, CVX_C1, CVX_B1);
    cudaEventRecord(evB, s0);

    // s1: gemm chunk1 after conv_x chunk1
    cudaStreamWaitEvent(s1, evB, 0);
    {
        dim3 g1(GB1, NOUT / BN);
        gemm_kernel<<<g1, 256, GEMM_SMEM, s1>>>(b1, GB0);
    }
    cudaEventRecord(evC, s1);

    // join: edge + finalize on S after all gemm work
    cudaStreamWaitEvent(s0, evC, 0);
    edge_kernel<<<EDGE_BLOCKS, 256, 0, s0>>>(W2, b2, cw, esrc, edst, labels, out);
    finalize_kernel<<<1, 256, 0, s0>>>(out);
}

// round 16
// speedup vs baseline: 1.0201x; 1.0201x over previous
#include <cuda_runtime.h>
#include <cuda_fp16.h>
#include <math.h>
#include <stdint.h>

// Problem constants (fixed by the dataset)
#define NNODES 50000
#define HDIM   768
#define D1DIM  256
#define NOUT   512        // 2*D1: [A | B] per node
#define NEDGES 200000

// GEMM tiling: 128x128 block, BK=32, fp16 mma.sync m16n8k16, 3-stage cp.async
#define BM 128
#define BN 128
#define BK 32
#define LDH 40            // smem row stride in halves (80B); conflict-free ldmatrix
#define NSTAGE 3
#define STAGE_H (BM * LDH)            // halves per tile stage (5120)

#define EDGE_WARPS 8
#define EDGES_PER_WARP 8
#define EDGES_PER_BLOCK (EDGE_WARPS * EDGES_PER_WARP)     // 64
#define EDGE_BLOCKS (NEDGES / EDGES_PER_BLOCK)            // 3125

// conv: x part (4 strided float4 per thread) + W part appended to the grid
#define CVX_UNROLL 4
#define CVX_N4 ((size_t)NNODES * HDIM / 4)                // 9,600,000 float4
#define CVX_BLOCKS ((int)((CVX_N4 + 256 * CVX_UNROLL - 1) / (256 * CVX_UNROLL)))  // 9375
#define CVW_N4 (NOUT * HDIM / 4)                          // 98304 float4
#define CVW_BLOCKS ((CVW_N4 + 255) / 256)                 // 384

// Scratch (static device globals; no runtime allocation)
__device__ __half g_xh[(size_t)NNODES * HDIM];       // x in fp16 (~77 MB)
__device__ __half g_Wh[(size_t)NOUT * HDIM];         // Wcat rows in fp16 (768 KB)
__device__ __half g_AB[(size_t)NNODES * NOUT];       // ~51 MB -> L2-resident
__device__ float  g_partials[2 * EDGE_BLOCKS];
__device__ unsigned g_ctr;                           // zero-init; self-resetting

// ---------------------------------------------------------------------------
// helpers
// ---------------------------------------------------------------------------
__device__ __forceinline__ void cp_async16(void* smem, const void* gmem) {
    unsigned s = (unsigned)__cvta_generic_to_shared(smem);
    asm volatile("cp.async.cg.shared.global [%0], [%1], 16;" :: "r"(s), "l"(gmem));
}
#define CP_COMMIT  asm volatile("cp.async.commit_group;")
#define CP_WAIT1   asm volatile("cp.async.wait_group 1;")
#define CP_WAIT0   asm volatile("cp.async.wait_group 0;")

__device__ __forceinline__ void ldsm_x4(unsigned& r0, unsigned& r1,
                                        unsigned& r2, unsigned& r3, unsigned addr) {
    asm volatile("ldmatrix.sync.aligned.m8n8.x4.shared.b16 {%0,%1,%2,%3}, [%4];"
                 : "=r"(r0), "=r"(r1), "=r"(r2), "=r"(r3) : "r"(addr));
}

#define MMA_F16(c, a, b)                                                      \
    asm volatile(                                                             \
        "mma.sync.aligned.m16n8k16.row.col.f32.f16.f16.f32 "                  \
        "{%0,%1,%2,%3},{%4,%5,%6,%7},{%8,%9},{%0,%1,%2,%3};"                  \
        : "+f"((c)[0]), "+f"((c)[1]), "+f"((c)[2]), "+f"((c)[3])              \
        : "r"((a)[0]), "r"((a)[1]), "r"((a)[2]), "r"((a)[3]),                 \
          "r"((b)[0]), "r"((b)[1]))

// packed half2 tanh on the MUFU pipe
__device__ __forceinline__ __half2 tanh_h2(__half2 x) {
    __half2 y;
    asm("tanh.approx.f16x2 %0, %1;"
        : "=r"(reinterpret_cast<unsigned&>(y))
        : "r"(reinterpret_cast<unsigned&>(x)));
    return y;
}

// ---------------------------------------------------------------------------
// Merged conversion pre-pass: blocks [0, CVX_BLOCKS) convert x,
// blocks [CVX_BLOCKS, CVX_BLOCKS+CVW_BLOCKS) convert Wcat.
// ---------------------------------------------------------------------------
__global__ __launch_bounds__(256) void conv_kernel(const float* __restrict__ x,
                                                   const float* __restrict__ W1)
{
    if (blockIdx.x < CVX_BLOCKS) {
        const size_t stride = (size_t)CVX_BLOCKS * 256;
        const size_t i = (size_t)blockIdx.x * 256 + threadIdx.x;
        float4 v[CVX_UNROLL];
        bool ok[CVX_UNROLL];
        size_t idx[CVX_UNROLL];
        #pragma unroll
        for (int u = 0; u < CVX_UNROLL; u++) {
            idx[u] = i + (size_t)u * stride;
            ok[u]  = idx[u] < CVX_N4;
            if (ok[u]) v[u] = *(const float4*)(x + idx[u] * 4);
        }
        #pragma unroll
        for (int u = 0; u < CVX_UNROLL; u++) {
            if (ok[u]) {
                __half2 h0 = __floats2half2_rn(v[u].x, v[u].y);
                __half2 h1 = __floats2half2_rn(v[u].z, v[u].w);
                uint2 o; o.x = *(uint32_t*)&h0; o.y = *(uint32_t*)&h1;
                *(uint2*)(g_xh + idx[u] * 4) = o;
            }
        }
    } else {
        const int i = (blockIdx.x - CVX_BLOCKS) * 256 + threadIdx.x;
        if (i < CVW_N4) {
            const int e = i * 4;
            const int n = e / HDIM;
            const int k = e % HDIM;
            const float* src = (n < D1DIM)
                ? (W1 + (size_t)n * (2 * HDIM) + k)
                : (W1 + (size_t)(n - D1DIM) * (2 * HDIM) + HDIM + k);
            float4 v = *(const float4*)src;
            __half2 h0 = __floats2half2_rn(v.x, v.y);
            __half2 h1 = __floats2half2_rn(v.z, v.w);
            uint2 o; o.x = *(uint32_t*)&h0; o.y = *(uint32_t*)&h1;
            *(uint2*)(g_Wh + e) = o;
        }
    }
}

// ---------------------------------------------------------------------------
// Kernel 1: AB = x_h @ W_h^T via fp16 mma.sync m16n8k16 (fp32 accumulate).
// 3-stage cp.async pipeline, ldmatrix.x4 b16 fragment loads.
// Epilogue folds b1 into the A-half (n0 < 256) in fp32 before fp16 rounding.
// ---------------------------------------------------------------------------
__global__ __launch_bounds__(256) void gemm_kernel(const float* __restrict__ b1)
{
    extern __shared__ __align__(16) __half smem[];
    __half* sA = smem;
    __half* sB = smem + NSTAGE * STAGE_H;

    const int tid  = threadIdx.x;
    const int lane = tid & 31;
    const int warp = tid >> 5;
    const int wm   = (warp >> 2) * 64;
    const int wn   = (warp & 3) * 32;

    const int m0 = blockIdx.x * BM;
    const int n0 = blockIdx.y * BN;

    const int row0 = tid >> 2;             // 0..63
    const int c4   = tid & 3;
    const int row1 = row0 + 64;
    int gm0 = m0 + row0; if (gm0 > NNODES - 1) gm0 = NNODES - 1;
    int gm1 = m0 + row1; if (gm1 > NNODES - 1) gm1 = NNODES - 1;
    const __half* pA0 = g_xh + (size_t)gm0 * HDIM + c4 * 8;
    const __half* pA1 = g_xh + (size_t)gm1 * HDIM + c4 * 8;
    const __half* pB0 = g_Wh + (size_t)(n0 + row0) * HDIM + c4 * 8;
    const __half* pB1 = g_Wh + (size_t)(n0 + row1) * HDIM + c4 * 8;

    unsigned smA[NSTAGE], smB[NSTAGE];
    #pragma unroll
    for (int st = 0; st < NSTAGE; st++) {
        smA[st] = (unsigned)__cvta_generic_to_shared(sA + st * STAGE_H);
        smB[st] = (unsigned)__cvta_generic_to_shared(sB + st * STAGE_H);
    }

    const int aRow = wm + (lane & 15);
    const unsigned aKB = (unsigned)(lane >> 4) * 16u;
    const int bRow = wn + ((lane >> 4) & 1) * 8 + (lane & 7);
    const unsigned bKB = (unsigned)((lane >> 3) & 1) * 16u;

    float acc[4][4][4];
    #pragma unroll
    for (int i = 0; i < 4; i++)
        #pragma unroll
        for (int j = 0; j < 4; j++)
            #pragma unroll
            for (int v = 0; v < 4; v++) acc[i][j][v] = 0.f;

    #pragma unroll
    for (int st = 0; st < 2; st++) {
        const int kt = st * BK;
        cp_async16(sA + st * STAGE_H + row0 * LDH + c4 * 8, pA0 + kt);
        cp_async16(sA + st * STAGE_H + row1 * LDH + c4 * 8, pA1 + kt);
        cp_async16(sB + st * STAGE_H + row0 * LDH + c4 * 8, pB0 + kt);
        cp_async16(sB + st * STAGE_H + row1 * LDH + c4 * 8, pB1 + kt);
        CP_COMMIT;
    }

    const int NIT = HDIM / BK;  // 24
    int s = 0;
    for (int it = 0; it < NIT; ++it) {
        if (it < NIT - 1) { CP_WAIT1; } else { CP_WAIT0; }
        __syncthreads();

        if (it + 2 < NIT) {
            const int st = (it + 2) % NSTAGE;
            const int kt = (it + 2) * BK;
            cp_async16(sA + st * STAGE_H + row0 * LDH + c4 * 8, pA0 + kt);
            cp_async16(sA + st * STAGE_H + row1 * LDH + c4 * 8, pA1 + kt);
            cp_async16(sB + st * STAGE_H + row0 * LDH + c4 * 8, pB0 + kt);
            cp_async16(sB + st * STAGE_H + row1 * LDH + c4 * 8, pB1 + kt);
            CP_COMMIT;
        }

        const unsigned bA = smA[s];
        const unsigned bB = smB[s];
        #pragma unroll
        for (int kk = 0; kk < 2; kk++) {
            unsigned af[4][4], bf[4][2];
            #pragma unroll
            for (int mi = 0; mi < 4; mi++) {
                unsigned addr = bA + (unsigned)(aRow + mi * 16) * (LDH * 2)
                              + (unsigned)kk * 32u + aKB;
                ldsm_x4(af[mi][0], af[mi][1], af[mi][2], af[mi][3], addr);
            }
            #pragma unroll
            for (int p = 0; p < 2; p++) {
                unsigned addr = bB + (unsigned)(bRow + p * 16) * (LDH * 2)
                              + (unsigned)kk * 32u + bKB;
                ldsm_x4(bf[2 * p][0], bf[2 * p][1], bf[2 * p + 1][0], bf[2 * p + 1][1], addr);
            }
            #pragma unroll
            for (int mi = 0; mi < 4; mi++)
                #pragma unroll
                for (int ni = 0; ni < 4; ni++)
                    MMA_F16(acc[mi][ni], af[mi], bf[ni]);
        }
        s = (s + 1 == NSTAGE) ? 0 : s + 1;
    }

    // ---- epilogue: fold b1 into A-half, store fp16 ----
    const int g  = lane >> 2;
    const int tg = lane & 3;
    const bool isA = (n0 < D1DIM);         // uniform per block (BN=128)
    float2 bv[4];
    #pragma unroll
    for (int ni = 0; ni < 4; ni++) {
        const int gn = n0 + wn + ni * 8 + 2 * tg;
        bv[ni] = isA ? *(const float2*)(b1 + gn) : make_float2(0.f, 0.f);
    }
    #pragma unroll
    for (int mi = 0; mi < 4; mi++) {
        #pragma unroll
        for (int ni = 0; ni < 4; ni++) {
            const int gm = m0 + wm + mi * 16 + g;
            const int gn = n0 + wn + ni * 8 + 2 * tg;
            if (gm < NNODES) {
                *(__half2*)(g_AB + (size_t)gm * NOUT + gn) =
                    __floats2half2_rn(acc[mi][ni][0] + bv[ni].x,
                                      acc[mi][ni][1] + bv[ni].y);
            }
            if (gm + 8 < NNODES) {
                *(__half2*)(g_AB + (size_t)(gm + 8) * NOUT + gn) =
                    __floats2half2_rn(acc[mi][ni][2] + bv[ni].x,
                                      acc[mi][ni][3] + bv[ni].y);
            }
        }
    }
}

// ---------------------------------------------------------------------------
// Kernel 2: per-edge MLP tail, packed half2, logit-difference form.
// 8 edges per warp (16 gathers in flight). Last block folds in the final
// loss reduction (atomicInc wraps -> counter self-resets across replays).
// ---------------------------------------------------------------------------
__global__ __launch_bounds__(256) void edge_kernel(const float* __restrict__ W2,
                                                   const float* __restrict__ b2,
                                                   const float* __restrict__ cw,
                                                   const int* __restrict__ esrc,
                                                   const int* __restrict__ edst,
                                                   const int* __restrict__ labels,
                                                   float* __restrict__ out)
{
    __shared__ __half2 s_wdh[D1DIM / 2];     // 0.5*(w1 - w0) in fp16
    __shared__ float s_wn[EDGE_WARPS];
    __shared__ float s_w[EDGE_WARPS];
    __shared__ bool  s_last;

    const int tid  = threadIdx.x;
    const int lane = tid & 31;
    const int warp = tid >> 5;

    if (tid < D1DIM / 2) {
        s_wdh[tid] = __floats2half2_rn(
            0.5f * (W2[D1DIM + 2 * tid]     - W2[2 * tid]),
            0.5f * (W2[D1DIM + 2 * tid + 1] - W2[2 * tid + 1]));
    }
    __syncthreads();

    const int eb = blockIdx.x * EDGES_PER_BLOCK + warp * EDGES_PER_WARP;
    const int j0 = lane * 8;          // 8 halves = 4 half2 per lane
    const int h0 = lane * 4;          // half2 base index

    // issue all 16 gathers before compute
    uint4 va[EDGES_PER_WARP], vb[EDGES_PER_WARP];
    #pragma unroll
    for (int q = 0; q < EDGES_PER_WARP; q++) {
        const int s = esrc[eb + q];
        const int d = edst[eb + q];
        va[q] = *(const uint4*)(g_AB + (size_t)s * NOUT + j0);
        vb[q] = *(const uint4*)(g_AB + (size_t)d * NOUT + D1DIM + j0);
    }

    const __half2 C0 = __float2half2_rn(0.7978845608f);
    const __half2 C1 = __float2half2_rn(0.0356774081f);

    __half2 acd[EDGES_PER_WARP];
    #pragma unroll
    for (int q = 0; q < EDGES_PER_WARP; q++) acd[q] = __float2half2_rn(0.f);

    #pragma unroll
    for (int t = 0; t < 4; t++) {
        const __half2 wd = s_wdh[h0 + t];
        #pragma unroll
        for (int q = 0; q < EDGES_PER_WARP; q++) {
            const __half2 a2  = ((const __half2*)&va[q])[t];   // b1 folded in
            const __half2 b2h = ((const __half2*)&vb[q])[t];
            const __half2 v  = __hadd2(a2, b2h);
            const __half2 w  = __hmul2(v, v);
            const __half2 u  = __hmul2(v, __hfma2(C1, w, C0));
            const __half2 th = tanh_h2(u);
            const __half2 h2 = __hfma2(v, th, v);              // = 2*gelu
            acd[q] = __hfma2(h2, wd, acd[q]);
        }
    }

    float r[EDGES_PER_WARP];
    #pragma unroll
    for (int q = 0; q < EDGES_PER_WARP; q++) {
        const float2 x = __half22float2(acd[q]);
        r[q] = x.x + x.y;
    }

    // ---- folded butterfly reduce: 8 values over 32 lanes in 13 shfl ----
    // after folds, lane l holds edge ((l>>4)&1)*4 + ((l>>3)&1)*2 + ((l>>2)&1)
    #pragma unroll
    for (int i = 0; i < 4; i++) {                       // xor 16: 8 -> 4
        const float keep = (lane & 16) ? r[i + 4] : r[i];
        const float send = (lane & 16) ? r[i] : r[i + 4];
        r[i] = keep + __shfl_xor_sync(0xFFFFFFFFu, send, 16);
    }
    #pragma unroll
    for (int i = 0; i < 2; i++) {                       // xor 8: 4 -> 2
        const float keep = (lane & 8) ? r[i + 2] : r[i];
        const float send = (lane & 8) ? r[i] : r[i + 2];
        r[i] = keep + __shfl_xor_sync(0xFFFFFFFFu, send, 8);
    }
    {                                                   // xor 4: 2 -> 1
        const float keep = (lane & 4) ? r[1] : r[0];
        const float send = (lane & 4) ? r[0] : r[1];
        r[0] = keep + __shfl_xor_sync(0xFFFFFFFFu, send, 4);
    }
    r[0] += __shfl_xor_sync(0xFFFFFFFFu, r[0], 2);
    r[0] += __shfl_xor_sync(0xFFFFFFFFu, r[0], 1);

    // ---- parallel epilogue: lanes 0,4,...,28 each own one edge ----
    float wn = 0.f, wsum = 0.f;
    if ((lane & 3) == 0) {
        const int q = ((lane >> 4) & 1) * 4 + ((lane >> 3) & 1) * 2 + ((lane >> 2) & 1);
        const int e = eb + q;
        const float d = r[0] + (__ldg(&b2[1]) - __ldg(&b2[0]));
        const float ed  = __expf(-fabsf(d));
        const float inv = 1.0f / (1.0f + ed);
        const float pmx = inv;
        const float pmn = ed * inv;
        const float p1 = (d >= 0.f) ? pmx : pmn;
        const float p0 = (d >= 0.f) ? pmn : pmx;
        out[1 + 2 * e]     = p0;
        out[1 + 2 * e + 1] = p1;
        const int lb = labels[e];
        const float py = lb ? p1 : p0;
        const float w  = __ldg(&cw[lb]);
        wn   = -w * logf(py);
        wsum = w;
    }
    // sum over the 8 owner lanes (others are 0)
    wn   += __shfl_xor_sync(0xFFFFFFFFu, wn, 4);
    wsum += __shfl_xor_sync(0xFFFFFFFFu, wsum, 4);
    wn   += __shfl_xor_sync(0xFFFFFFFFu, wn, 8);
    wsum += __shfl_xor_sync(0xFFFFFFFFu, wsum, 8);
    wn   += __shfl_xor_sync(0xFFFFFFFFu, wn, 16);
    wsum += __shfl_xor_sync(0xFFFFFFFFu, wsum, 16);

    if (lane == 0) { s_wn[warp] = wn; s_w[warp] = wsum; }
    __syncthreads();
    if (tid == 0) {
        float a = 0.f, b = 0.f;
        #pragma unroll
        for (int i = 0; i < EDGE_WARPS; i++) { a += s_wn[i]; b += s_w[i]; }
        g_partials[blockIdx.x]               = a;
        g_partials[EDGE_BLOCKS + blockIdx.x] = b;
        __threadfence();
        // self-resetting completion counter (wraps to 0 at EDGE_BLOCKS-1)
        const unsigned old = atomicInc(&g_ctr, EDGE_BLOCKS - 1);
        s_last = (old == EDGE_BLOCKS - 1);
    }
    __syncthreads();

    // ---- last block: deterministic final reduction -> loss at out[0] ----
    if (s_last) {
        __shared__ float sa[256];
        __shared__ float sb[256];
        float a = 0.f, b = 0.f;
        for (int i = tid; i < EDGE_BLOCKS; i += 256) {
            a += g_partials[i];
            b += g_partials[EDGE_BLOCKS + i];
        }
        sa[tid] = a; sb[tid] = b;
        __syncthreads();
        for (int o = 128; o > 0; o >>= 1) {
            if (tid < o) { sa[tid] += sa[tid + o]; sb[tid] += sb[tid + o]; }
            __syncthreads();
        }
        if (tid == 0) out[0] = sa[0] / sb[0];
    }
}

// ---------------------------------------------------------------------------
extern "C" void kernel_launch(void* const* d_in, const int* in_sizes, int n_in,
                              void* d_out, int out_size)
{
    const float* x      = (const float*)d_in[0];
    const float* W1     = (const float*)d_in[1];
    const float* b1     = (const float*)d_in[2];
    const float* W2     = (const float*)d_in[3];
    const float* b2     = (const float*)d_in[4];
    const float* cw     = (const float*)d_in[5];
    const int*   esrc   = (const int*)d_in[6];
    const int*   edst   = (const int*)d_in[7];
    const int*   labels = (const int*)d_in[8];
    float* out = (float*)d_out;

    const int GEMM_SMEM = 2 * NSTAGE * STAGE_H * (int)sizeof(__half);  // 61440
    cudaFuncSetAttribute(gemm_kernel,
                         cudaFuncAttributeMaxDynamicSharedMemorySize, GEMM_SMEM);

    conv_kernel<<<CVX_BLOCKS + CVW_BLOCKS, 256>>>(x, W1);

    dim3 ggrid((NNODES + BM - 1) / BM, NOUT / BN);   // 391 x 4
    gemm_kernel<<<ggrid, 256, GEMM_SMEM>>>(b1);
    edge_kernel<<<EDGE_BLOCKS, 256>>>(W2, b2, cw, esrc, edst, labels, out);
}